// round 12
// baseline (speedup 1.0000x reference)
#include <cuda_runtime.h>

// MALIS pseudo-loss, restructured:
//   loss = -0.5 * sum_b [ sum_{Kruskal merges, desc affinity} nz_u*nz_v*a  -  sum_{l>=1} C(c_l,2) ]
// nz = nonzero-label voxel count of a component; c_l = label-l count per image.
//
// Kernel 1 (malis_sort): pack (key32 | idx16) into u64, 3-pass 8-bit LSD radix
//   over key bits [8,32) (tie order is provably irrelevant to the sum), warp-
//   interleaved layout for full coalescing, match_any-based stable ranks.
// Kernel 2 (malis_kruskal): single-warp root-claiming Kruskal, 32-edge batches,
//   prefetched u64 pair loads. Lanes claim their two component roots with
//   atomicMin(lane); a lane winning both claims is the highest-affinity edge
//   touching those components and merges in parallel with all other
//   (root-disjoint) winners; losers retry => exact serial Kruskal order.

namespace {
constexpr int NB       = 2;
constexpr int HH       = 128;
constexpr int WW       = 128;
constexpr int NNODE    = HH * WW;      // 16384
constexpr int NEDGE    = 2 * NNODE;    // 32768
constexpr int STHREADS = 1024;         // sort kernel threads
constexpr int KTHREADS = 256;          // kruskal kernel threads (init helpers)
constexpr int WARPS    = STHREADS / 32;      // 32
constexpr int IPW      = NEDGE / WARPS;      // 1024 items per warp
constexpr int JITER    = IPW / 32;           // 32 items per lane
constexpr unsigned FULL = 0xFFFFFFFFu;

struct KSmem {
    unsigned int   szn[NNODE];      // size (low 16) | nonzero-count (high 16)
    unsigned int   claim[NNODE];    // claim slots (lane, FULL = free)
    unsigned short parent[NNODE];   // union-find parent
    int            hist[64];
    int            flag64;
};
} // namespace

__device__ __align__(16) unsigned long long g_pairA[NB][NEDGE];
__device__ __align__(16) unsigned long long g_pairB[NB][NEDGE];
__device__ double g_res[NB];

// Find with path halving. Concurrent halving writes are safe: every stored
// parent is an observed ancestor, and ancestor sets only grow. With no merges
// concurrent to the find, the returned value is the exact current root.
static __device__ __forceinline__ int uf_find_halve(unsigned short* parent, int x) {
    for (;;) {
        int p = parent[x];
        if (p == x) return x;
        int g = parent[p];
        if (g == p) return p;
        parent[x] = (unsigned short)g;
        x = g;
    }
}

// ---------------------------------------------------------------------------
// Kernel 1: build packed pairs + 3-pass 8-bit radix sort (ascending key ==
// descending affinity). Final sorted data lands in g_pairB.
// ---------------------------------------------------------------------------
__global__ __launch_bounds__(STHREADS, 1)
void malis_sort(const float* __restrict__ aff) {
    __shared__ unsigned int hist[256 * WARPS];   // 32 KB
    __shared__ unsigned int warpAgg[32];

    const int b    = blockIdx.x;
    const int tid  = threadIdx.x;
    const int lane = tid & 31;
    const int w    = tid >> 5;

    unsigned long long* A = g_pairA[b];
    unsigned long long* B = g_pairB[b];
    const float* affb = aff + (size_t)b * NEDGE;

    // build packed (key << 16 | idx); key = order-transformed float, inverted
    for (int e = tid; e < NEDGE; e += STHREADS) {
        unsigned u = __float_as_uint(affb[e]);
        unsigned o = (u & 0x80000000u) ? ~u : (u | 0x80000000u);
        unsigned key = ~o;                       // ascending key = descending float
        A[e] = ((unsigned long long)key << 16) | (unsigned)e;
    }
    __syncthreads();

    unsigned long long* src = A;
    unsigned long long* dst = B;

    #pragma unroll
    for (int p = 0; p < 3; ++p) {
        const int shift = 24 + p * 8;            // key bits [8,32)

        for (int k = tid; k < 256 * WARPS; k += STHREADS) hist[k] = 0;
        __syncthreads();

        const unsigned long long* sp = src + w * IPW + lane;   // warp-interleaved

        // count (order irrelevant -> shared atomics)
        for (int j = 0; j < JITER; ++j) {
            unsigned d = (unsigned)(sp[j * 32] >> shift) & 255u;
            atomicAdd(&hist[d * WARPS + w], 1u);
        }
        __syncthreads();

        // exclusive scan of 8192 counters in (digit-major, warp-minor) order
        unsigned vals[8], sum = 0;
        {
            const int base = tid * 8;
            #pragma unroll
            for (int i = 0; i < 8; ++i) { vals[i] = hist[base + i]; sum += vals[i]; }
        }
        unsigned x = sum;
        #pragma unroll
        for (int d = 1; d < 32; d <<= 1) {
            unsigned y = __shfl_up_sync(FULL, x, d);
            if (lane >= d) x += y;
        }
        if (lane == 31) warpAgg[w] = x;
        __syncthreads();
        if (w == 0) {
            unsigned ww = warpAgg[lane];
            #pragma unroll
            for (int d = 1; d < 32; d <<= 1) {
                unsigned y = __shfl_up_sync(FULL, ww, d);
                if (lane >= d) ww += y;
            }
            warpAgg[lane] = ww;
        }
        __syncthreads();
        {
            unsigned excl = ((w > 0) ? warpAgg[w - 1] : 0u) + (x - sum);
            const int base = tid * 8;
            unsigned run = excl;
            #pragma unroll
            for (int i = 0; i < 8; ++i) { hist[base + i] = run; run += vals[i]; }
        }
        __syncthreads();

        // stable scatter: per j-step, match lanes with equal digit; group leader
        // bumps the per-(digit,warp) running offset; lanes place at base+rank.
        for (int j = 0; j < JITER; ++j) {
            unsigned long long v = sp[j * 32];
            unsigned d = (unsigned)(v >> shift) & 255u;
            unsigned mask = __match_any_sync(FULL, d);
            int leader = __ffs(mask) - 1;
            unsigned prior = __popc(mask & ((1u << lane) - 1u));
            unsigned base = 0;
            if (lane == leader) {
                base = hist[d * WARPS + w];
                hist[d * WARPS + w] = base + __popc(mask);
            }
            base = __shfl_sync(mask, base, leader);
            dst[base + prior] = v;
        }
        __syncthreads();

        unsigned long long* t = src; src = dst; dst = t;
    }
    // passes: A->B, B->A, A->B  =>  sorted result in g_pairB
}

// ---------------------------------------------------------------------------
// Kernel 2: single-warp claiming Kruskal with prefetched pair loads
// ---------------------------------------------------------------------------
__global__ __launch_bounds__(KTHREADS, 1)
void malis_kruskal(const void* __restrict__ gt) {
    extern __shared__ unsigned char raw[];
    KSmem* s = reinterpret_cast<KSmem*>(raw);

    const int b    = blockIdx.x;
    const int tid  = threadIdx.x;
    const int lane = tid & 31;
    const int wid  = tid >> 5;

    // groundtruth dtype detection (int64 vs int32); labels in [0,64)
    if (tid == 0) {
        int is64 = 1;
        const long long* g64 = (const long long*)gt;
        for (int i = 0; i < 128; ++i) {
            long long v = g64[i];
            if (v < 0 || v > 63) { is64 = 0; break; }
        }
        s->flag64 = is64;
    }
    if (tid < 64) s->hist[tid] = 0;
    __syncthreads();

    const int f64 = s->flag64;
    for (int n = tid; n < NNODE; n += KTHREADS) {
        int lab = f64 ? (int)((const long long*)gt)[(size_t)b * NNODE + n]
                      : ((const int*)gt)[(size_t)b * NNODE + n];
        s->parent[n] = (unsigned short)n;
        s->szn[n]    = 1u | ((lab != 0) ? (1u << 16) : 0u);
        s->claim[n]  = FULL;
        atomicAdd(&s->hist[lab & 63], 1);
    }
    __syncthreads();

    if (wid == 0) {
        const unsigned long long* P = g_pairB[b];
        double S = 0.0;
        int mergeCnt = 0;

        unsigned long long cur = P[lane];          // prefetch batch 0

        for (int c0 = 0; c0 < NEDGE; c0 += 32) {
            // prefetch next batch early (clamped; independent of processing)
            const int nc = (c0 + 32 < NEDGE) ? c0 + 32 : c0;
            const unsigned long long nxt = P[nc + lane];

            const int idx = (int)(cur & 0xFFFFu);
            const unsigned key = (unsigned)(cur >> 16);

            // decode edge endpoints (matches reference _edges)
            int u, v;
            if (idx < NNODE) {                         // channel 0: (i,j)-(i+1,j)
                u = idx; v = idx + WW;
                if (idx >= NNODE - WW) { u = 0; v = 0; }
            } else {                                   // channel 1: (i,j)-(i,j+1)
                const int t2 = idx - NNODE;
                u = t2; v = t2 + 1;
                if ((t2 & (WW - 1)) == (WW - 1)) { u = 0; v = 0; }
            }

            // exact affinity recovery (full 32 key bits preserved)
            const unsigned o = ~key;
            const float a = (o & 0x80000000u) ? __uint_as_float(o & 0x7FFFFFFFu)
                                              : __uint_as_float(~o);

            // exact root finds (no merges concurrent with finds)
            int ru = uf_find_halve(s->parent, u);
            int rv = uf_find_halve(s->parent, v);

            bool active = (ru != rv);
            unsigned actmask = __ballot_sync(FULL, active);

            while (actmask) {
                if (active) {
                    atomicMin(&s->claim[ru], (unsigned)lane);
                    atomicMin(&s->claim[rv], (unsigned)lane);
                }
                __syncwarp();

                bool win = false;
                if (active)
                    win = (s->claim[ru] == (unsigned)lane) && (s->claim[rv] == (unsigned)lane);

                if (win) {
                    // winners are pairwise root-disjoint: all writes disjoint
                    const unsigned z1 = s->szn[ru], z2 = s->szn[rv];
                    int big, small; unsigned zb, zs;
                    if ((z1 & 0xFFFFu) >= (z2 & 0xFFFFu)) { big = ru; small = rv; zb = z1; zs = z2; }
                    else                                   { big = rv; small = ru; zb = z2; zs = z1; }
                    s->parent[small] = (unsigned short)big;
                    s->szn[big] = zb + zs;   // sz<=16384, nz<=sz: no cross-field carry
                    S += (double)((zs >> 16) * (zb >> 16)) * (double)a;
                    s->parent[u] = (unsigned short)big;   // endpoint compression
                    s->parent[v] = (unsigned short)big;   // (endpoints unique among winners)
                }
                __syncwarp();

                // reset claims (shared resets write the same value: benign)
                if (active) { s->claim[ru] = FULL; s->claim[rv] = FULL; }

                mergeCnt += __popc(__ballot_sync(FULL, win));
                if (win) active = false;
                __syncwarp();

                if (active) {
                    // losers: re-resolve against post-merge state
                    ru = uf_find_halve(s->parent, ru);
                    rv = uf_find_halve(s->parent, rv);
                    if (ru == rv) active = false;   // became a cycle edge
                }
                actmask = __ballot_sync(FULL, active);
            }

            if (mergeCnt == NNODE - 1) break;   // MST complete: rest are cycle edges
            cur = nxt;
        }

        // warp reduction of per-lane partial sums
        #pragma unroll
        for (int d = 16; d > 0; d >>= 1)
            S += __shfl_xor_sync(FULL, S, d);

        if (lane == 0) {
            double Ploc = 0.0;
            for (int l = 1; l < 64; ++l) {
                double c = (double)s->hist[l];
                Ploc += 0.5 * c * (c - 1.0);
            }
            g_res[b] = S - Ploc;
        }
    }
}

__global__ void malis_finalize(float* __restrict__ out) {
    out[0] = (float)(-0.5 * (g_res[0] + g_res[1]));
}

extern "C" void kernel_launch(void* const* d_in, const int* in_sizes, int n_in,
                              void* d_out, int out_size) {
    const float* aff = (const float*)d_in[0];
    const void*  gt  = d_in[1];
    (void)in_sizes; (void)n_in; (void)out_size;

    const int ksmem = (int)sizeof(KSmem);
    cudaFuncSetAttribute(malis_kruskal, cudaFuncAttributeMaxDynamicSharedMemorySize, ksmem);

    malis_sort<<<NB, STHREADS>>>(aff);
    malis_kruskal<<<NB, KTHREADS, ksmem>>>(gt);
    malis_finalize<<<1, 1>>>((float*)d_out);
}

// round 15
// speedup vs baseline: 1.0387x; 1.0387x over previous
#include <cuda_runtime.h>

// MALIS pseudo-loss, restructured:
//   loss = -0.5 * sum_b [ sum_{Kruskal merges, desc affinity} nz_u*nz_v*a  -  sum_{l>=1} C(c_l,2) ]
// nz = nonzero-label voxel count of a component; c_l = label-l count per image.
//
// Kernel 1 (malis_sort): pack (key32 | idx16) into u64, 3-pass 8-bit LSD radix
//   over key bits [8,32) (tie order provably irrelevant), warp-interleaved
//   coalesced layout, match_any-based stable ranks.
// Kernel 2 (malis_kruskal): single-warp Kruskal with BITMASK claims + chain
//   fast-path. Lanes OR their bit into claim[root]; lowest claimant = head.
//   win-both lanes merge standard. Lanes winning exactly one root (o) and
//   losing the other (g) merge IN THE SAME ROUND as a chain into g's merged
//   component when: g's head won both roots, and every lower-lane claimant of
//   g / of head's other root is an accounted chain member. Contribution uses a
//   prefix sum of nz over lower chain members == exact serial Kruskal order.

namespace {
constexpr int NB       = 2;
constexpr int HH       = 128;
constexpr int WW       = 128;
constexpr int NNODE    = HH * WW;      // 16384
constexpr int NEDGE    = 2 * NNODE;    // 32768
constexpr int STHREADS = 1024;
constexpr int KTHREADS = 256;          // init helpers; warp 0 runs kruskal
constexpr int WARPS    = STHREADS / 32;      // 32
constexpr int IPW      = NEDGE / WARPS;      // 1024
constexpr int JITER    = IPW / 32;           // 32
constexpr unsigned FULL = 0xFFFFFFFFu;

struct KSmem {
    unsigned int   szn[NNODE];      // size (low 16) | nonzero-count (high 16)
    unsigned int   claim[NNODE];    // claimant bitmask per root (0 = free)
    unsigned short parent[NNODE];   // union-find parent
    unsigned int   stage[32];       // per-lane packed szn of won root (chain prefix)
    int            hist[64];
    int            flag64;
};
} // namespace

__device__ __align__(16) unsigned long long g_pairA[NB][NEDGE];
__device__ __align__(16) unsigned long long g_pairB[NB][NEDGE];
__device__ double g_res[NB];

// Find with path halving. Concurrent halving writes are safe: every stored
// parent is an observed ancestor, and ancestor sets only grow. With merges
// only at round boundaries (sync-separated), results are exact roots.
static __device__ __forceinline__ int uf_find_halve(unsigned short* parent, int x) {
    for (;;) {
        int p = parent[x];
        if (p == x) return x;
        int g = parent[p];
        if (g == p) return p;
        parent[x] = (unsigned short)g;
        x = g;
    }
}

// ---------------------------------------------------------------------------
// Kernel 1: 3-pass 8-bit LSD radix sort of packed (key<<16 | idx). Result in
// g_pairB (A->B, B->A, A->B).
// ---------------------------------------------------------------------------
__global__ __launch_bounds__(STHREADS, 1)
void malis_sort(const float* __restrict__ aff) {
    __shared__ unsigned int hist[256 * WARPS];   // 32 KB
    __shared__ unsigned int warpAgg[32];

    const int b    = blockIdx.x;
    const int tid  = threadIdx.x;
    const int lane = tid & 31;
    const int w    = tid >> 5;

    unsigned long long* A = g_pairA[b];
    unsigned long long* B = g_pairB[b];
    const float* affb = aff + (size_t)b * NEDGE;

    for (int e = tid; e < NEDGE; e += STHREADS) {
        unsigned u = __float_as_uint(affb[e]);
        unsigned o = (u & 0x80000000u) ? ~u : (u | 0x80000000u);
        unsigned key = ~o;                       // ascending key = descending float
        A[e] = ((unsigned long long)key << 16) | (unsigned)e;
    }
    __syncthreads();

    unsigned long long* src = A;
    unsigned long long* dst = B;

    #pragma unroll
    for (int p = 0; p < 3; ++p) {
        const int shift = 24 + p * 8;            // key bits [8,32)

        for (int k = tid; k < 256 * WARPS; k += STHREADS) hist[k] = 0;
        __syncthreads();

        const unsigned long long* sp = src + w * IPW + lane;

        for (int j = 0; j < JITER; ++j) {
            unsigned d = (unsigned)(sp[j * 32] >> shift) & 255u;
            atomicAdd(&hist[d * WARPS + w], 1u);
        }
        __syncthreads();

        unsigned vals[8], sum = 0;
        {
            const int base = tid * 8;
            #pragma unroll
            for (int i = 0; i < 8; ++i) { vals[i] = hist[base + i]; sum += vals[i]; }
        }
        unsigned x = sum;
        #pragma unroll
        for (int d = 1; d < 32; d <<= 1) {
            unsigned y = __shfl_up_sync(FULL, x, d);
            if (lane >= d) x += y;
        }
        if (lane == 31) warpAgg[w] = x;
        __syncthreads();
        if (w == 0) {
            unsigned ww = warpAgg[lane];
            #pragma unroll
            for (int d = 1; d < 32; d <<= 1) {
                unsigned y = __shfl_up_sync(FULL, ww, d);
                if (lane >= d) ww += y;
            }
            warpAgg[lane] = ww;
        }
        __syncthreads();
        {
            unsigned excl = ((w > 0) ? warpAgg[w - 1] : 0u) + (x - sum);
            const int base = tid * 8;
            unsigned run = excl;
            #pragma unroll
            for (int i = 0; i < 8; ++i) { hist[base + i] = run; run += vals[i]; }
        }
        __syncthreads();

        for (int j = 0; j < JITER; ++j) {
            unsigned long long v = sp[j * 32];
            unsigned d = (unsigned)(v >> shift) & 255u;
            unsigned mask = __match_any_sync(FULL, d);
            int leader = __ffs(mask) - 1;
            unsigned prior = __popc(mask & ((1u << lane) - 1u));
            unsigned base = 0;
            if (lane == leader) {
                base = hist[d * WARPS + w];
                hist[d * WARPS + w] = base + __popc(mask);
            }
            base = __shfl_sync(mask, base, leader);
            dst[base + prior] = v;
        }
        __syncthreads();

        unsigned long long* t = src; src = dst; dst = t;
    }
}

// ---------------------------------------------------------------------------
// Kernel 2: single-warp bitmask-claim Kruskal with chain fast-path
// ---------------------------------------------------------------------------
__global__ __launch_bounds__(KTHREADS, 1)
void malis_kruskal(const void* __restrict__ gt) {
    extern __shared__ unsigned char raw[];
    KSmem* s = reinterpret_cast<KSmem*>(raw);

    const int b    = blockIdx.x;
    const int tid  = threadIdx.x;
    const int lane = tid & 31;
    const int wid  = tid >> 5;

    // groundtruth dtype detection (int64 vs int32); labels in [0,64)
    if (tid == 0) {
        int is64 = 1;
        const long long* g64 = (const long long*)gt;
        for (int i = 0; i < 128; ++i) {
            long long v = g64[i];
            if (v < 0 || v > 63) { is64 = 0; break; }
        }
        s->flag64 = is64;
    }
    if (tid < 64) s->hist[tid] = 0;
    __syncthreads();

    const int f64 = s->flag64;
    for (int n = tid; n < NNODE; n += KTHREADS) {
        int lab = f64 ? (int)((const long long*)gt)[(size_t)b * NNODE + n]
                      : ((const int*)gt)[(size_t)b * NNODE + n];
        s->parent[n] = (unsigned short)n;
        s->szn[n]    = 1u | ((lab != 0) ? (1u << 16) : 0u);
        s->claim[n]  = 0u;
        atomicAdd(&s->hist[lab & 63], 1);
    }
    __syncthreads();

    if (wid == 0) {
        const unsigned long long* P = g_pairB[b];
        unsigned short* parent = s->parent;
        double S = 0.0;
        int mergeCnt = 0;
        const unsigned bit = 1u << lane;
        const unsigned below = bit - 1u;

        unsigned long long cur = P[lane];          // prefetch batch 0

        for (int c0 = 0; c0 < NEDGE; c0 += 32) {
            const int nc = (c0 + 32 < NEDGE) ? c0 + 32 : c0;
            const unsigned long long nxt = P[nc + lane];

            const int idx = (int)(cur & 0xFFFFu);
            const unsigned key = (unsigned)(cur >> 16);

            // decode edge endpoints (matches reference _edges)
            int u, v;
            if (idx < NNODE) {                         // channel 0: (i,j)-(i+1,j)
                u = idx; v = idx + WW;
                if (idx >= NNODE - WW) { u = 0; v = 0; }
            } else {                                   // channel 1: (i,j)-(i,j+1)
                const int t2 = idx - NNODE;
                u = t2; v = t2 + 1;
                if ((t2 & (WW - 1)) == (WW - 1)) { u = 0; v = 0; }
            }

            // exact affinity recovery (full 32 key bits preserved)
            const unsigned okey = ~key;
            const float a = (okey & 0x80000000u) ? __uint_as_float(okey & 0x7FFFFFFFu)
                                                 : __uint_as_float(~okey);

            int ru = uf_find_halve(parent, u);
            int rv = uf_find_halve(parent, v);

            bool active = (ru != rv);
            unsigned actmask = __ballot_sync(FULL, active);

            while (actmask) {
                // ---- claim phase: bitmask OR into both roots ----
                if (active) {
                    atomicOr(&s->claim[ru], bit);
                    atomicOr(&s->claim[rv], bit);
                }
                __syncwarp();

                unsigned mu = 0, mv = 0;
                if (active) { mu = s->claim[ru]; mv = s->claim[rv]; }
                const bool headU = active && ((mu & (0u - mu)) == bit);
                const bool headV = active && ((mv & (0u - mv)) == bit);
                const bool winB  = headU && headV;
                const bool wonOne = active && (headU != headV);

                // chain candidate data (garbage unless wonOne)
                const int gR = headU ? rv : ru;     // lost root
                const int oR = headU ? ru : rv;     // won root
                const unsigned mg = headU ? mv : mu;

                // publish packed szn of won root for chain prefix sums
                unsigned zo = 0;
                if (wonOne) zo = s->szn[oR];
                s->stage[lane] = zo;

                // group chain candidates by lost root (sentinel keeps others apart)
                const int matchval = wonOne ? gR : (0x20000 + lane);
                const unsigned grp = __match_any_sync(FULL, matchval);

                const int h = wonOne ? (__ffs(mg) - 1) : 0;   // head lane of g
                const unsigned wbM = __ballot_sync(FULL, winB);
                const bool headOK = wonOne && ((wbM >> h) & 1u);

                // win-both lanes: standard merge prep (union by size)
                unsigned z1 = 0, z2 = 0;
                if (winB) { z1 = s->szn[ru]; z2 = s->szn[rv]; }
                int Rw = 0, smallw = 0; unsigned zsumw = 0, zsw = 0;
                if (winB) {
                    if ((z1 & 0xFFFFu) >= (z2 & 0xFFFFu)) { Rw = ru; smallw = rv; zsw = z2; }
                    else                                   { Rw = rv; smallw = ru; zsw = z1; }
                    zsumw = z1 + z2;    // packed; sz<=16384, nz<=sz: no carry
                }

                // broadcast head's pair / chosen root / merged size
                const int hsrc = headOK ? h : 0;
                const int hru  = __shfl_sync(FULL, ru, hsrc);
                const int hrv  = __shfl_sync(FULL, rv, hsrc);
                const int Rh   = __shfl_sync(FULL, Rw, hsrc);
                const unsigned hzsum = __shfl_sync(FULL, zsumw, hsrc);

                const int oh = (gR == hru) ? hrv : hru;       // head's other root
                unsigned moh = 0;
                if (headOK) moh = s->claim[oh];

                // raw chain qualification: all lower claimants of g are {head} U grp,
                // and no lower claimant of head's other root besides head.
                const bool rawOK = headOK
                    && ((mg  & below & ~grp & ~(1u << h)) == 0u)
                    && ((moh & below & ~(1u << h)) == 0u);

                // a blocked lower group member blocks everyone above it
                const unsigned blockedM = __ballot_sync(FULL, wonOne && !rawOK);
                const bool qual = rawOK && ((blockedM & grp & below) == 0u);
                const unsigned qM = __ballot_sync(FULL, qual);

                // prefix of packed szn over qualified lower own-group members
                unsigned prefZ = 0;
                if (qual) {
                    unsigned pm = qM & grp & below;
                    while (pm) {
                        int j = __ffs(pm) - 1; pm &= pm - 1;
                        prefZ += s->stage[j];
                    }
                }

                // ---- merge phase (all roots touched are pairwise disjoint across
                //      winners; sizes read pre-merge; size updates atomic) ----
                if (winB) {
                    parent[smallw] = (unsigned short)Rw;
                    atomicAdd(&s->szn[Rw], zsw);
                    S += (double)((z1 >> 16) * (z2 >> 16)) * (double)a;
                    parent[u] = (unsigned short)Rw;
                    parent[v] = (unsigned short)Rw;
                }
                if (qual) {
                    parent[oR] = (unsigned short)Rh;
                    atomicAdd(&s->szn[Rh], zo);
                    const unsigned basenz = (hzsum >> 16) + (prefZ >> 16);
                    S += (double)((zo >> 16) * basenz) * (double)a;
                    parent[u] = (unsigned short)Rh;
                    parent[v] = (unsigned short)Rh;
                }
                __syncwarp();

                // reset claims (duplicate zero-writes benign)
                if (active) { s->claim[ru] = 0u; s->claim[rv] = 0u; }

                mergeCnt += __popc(wbM) + __popc(qM);
                if (winB || qual) active = false;
                __syncwarp();

                if (active) {
                    ru = uf_find_halve(parent, ru);
                    rv = uf_find_halve(parent, rv);
                    if (ru == rv) active = false;   // became a cycle edge
                }
                actmask = __ballot_sync(FULL, active);
            }

            if (mergeCnt == NNODE - 1) break;   // MST complete: rest are cycle edges
            cur = nxt;
        }

        // warp reduction of per-lane partial sums
        #pragma unroll
        for (int d = 16; d > 0; d >>= 1)
            S += __shfl_xor_sync(FULL, S, d);

        if (lane == 0) {
            double Ploc = 0.0;
            for (int l = 1; l < 64; ++l) {
                double c = (double)s->hist[l];
                Ploc += 0.5 * c * (c - 1.0);
            }
            g_res[b] = S - Ploc;
        }
    }
}

__global__ void malis_finalize(float* __restrict__ out) {
    out[0] = (float)(-0.5 * (g_res[0] + g_res[1]));
}

extern "C" void kernel_launch(void* const* d_in, const int* in_sizes, int n_in,
                              void* d_out, int out_size) {
    const float* aff = (const float*)d_in[0];
    const void*  gt  = d_in[1];
    (void)in_sizes; (void)n_in; (void)out_size;

    const int ksmem = (int)sizeof(KSmem);
    cudaFuncSetAttribute(malis_kruskal, cudaFuncAttributeMaxDynamicSharedMemorySize, ksmem);

    malis_sort<<<NB, STHREADS>>>(aff);
    malis_kruskal<<<NB, KTHREADS, ksmem>>>(gt);
    malis_finalize<<<1, 1>>>((float*)d_out);
}

// round 16
// speedup vs baseline: 1.3509x; 1.3005x over previous
#include <cuda_runtime.h>

// MALIS pseudo-loss, restructured:
//   loss = -0.5 * sum_b [ sum_{Kruskal merges, desc affinity} nz_u*nz_v*a  -  sum_{l>=1} C(c_l,2) ]
// nz = nonzero-label voxel count of a component; c_l = label-l count per image.
//
// Kernel 1 (malis_sort): pack (key32 | idx16) into u64, 3-pass 8-bit LSD radix
//   over key bits [8,32) (tie order provably irrelevant), warp-interleaved
//   coalesced layout, match_any-based stable ranks.
// Kernel 2 (malis_kruskal): hybrid front/back end.
//   Front (256 threads): per super-batch of 256 edges, parallel load + decode +
//     path-halving finds (latency amortized 8-way), staged to shared.
//   Back (warp 0): consumes 8 sub-batches of 32 via the bitmask-claim + chain
//     protocol; finds reduce to 1-2 LDS touch-ups from staged spec roots.
//   Chain fast-path: lanes OR their bit into claim[root]; lowest claimant =
//   head; win-both lanes merge standard; won-one lanes whose lost root's head
//   won both merge the same round with prefix-sum contributions == exact
//   serial Kruskal order.

namespace {
constexpr int NB       = 2;
constexpr int HH       = 128;
constexpr int WW       = 128;
constexpr int NNODE    = HH * WW;      // 16384
constexpr int NEDGE    = 2 * NNODE;    // 32768
constexpr int STHREADS = 1024;
constexpr int KTHREADS = 256;          // super-batch size
constexpr int WARPS    = STHREADS / 32;      // 32
constexpr int IPW      = NEDGE / WARPS;      // 1024
constexpr int JITER    = IPW / 32;           // 32
constexpr unsigned FULL = 0xFFFFFFFFu;

struct KSmem {
    unsigned int   szn[NNODE];      // size (low 16) | nonzero-count (high 16)
    unsigned int   claim[NNODE];    // claimant bitmask per root (0 = free)
    unsigned short parent[NNODE];   // union-find parent
    int            sU[KTHREADS], sV[KTHREADS];
    int            sRu[KTHREADS], sRv[KTHREADS];
    float          sAf[KTHREADS];
    unsigned int   stage[32];       // per-lane packed szn of won root (chain prefix)
    int            hist[64];
    int            flag64, sDone;
};
} // namespace

__device__ __align__(16) unsigned long long g_pairA[NB][NEDGE];
__device__ __align__(16) unsigned long long g_pairB[NB][NEDGE];
__device__ double g_res[NB];

// Find with path halving. Concurrent halving writes are safe: every stored
// parent is an observed ancestor, and ancestor sets only grow. With merges
// separated from finds by barriers, results are exact roots.
static __device__ __forceinline__ int uf_find_halve(unsigned short* parent, int x) {
    for (;;) {
        int p = parent[x];
        if (p == x) return x;
        int g = parent[p];
        if (g == p) return p;
        parent[x] = (unsigned short)g;
        x = g;
    }
}

// ---------------------------------------------------------------------------
// Kernel 1: 3-pass 8-bit LSD radix sort of packed (key<<16 | idx). Result in
// g_pairB (A->B, B->A, A->B).
// ---------------------------------------------------------------------------
__global__ __launch_bounds__(STHREADS, 1)
void malis_sort(const float* __restrict__ aff) {
    __shared__ unsigned int hist[256 * WARPS];   // 32 KB
    __shared__ unsigned int warpAgg[32];

    const int b    = blockIdx.x;
    const int tid  = threadIdx.x;
    const int lane = tid & 31;
    const int w    = tid >> 5;

    unsigned long long* A = g_pairA[b];
    unsigned long long* B = g_pairB[b];
    const float* affb = aff + (size_t)b * NEDGE;

    for (int e = tid; e < NEDGE; e += STHREADS) {
        unsigned u = __float_as_uint(affb[e]);
        unsigned o = (u & 0x80000000u) ? ~u : (u | 0x80000000u);
        unsigned key = ~o;                       // ascending key = descending float
        A[e] = ((unsigned long long)key << 16) | (unsigned)e;
    }
    __syncthreads();

    unsigned long long* src = A;
    unsigned long long* dst = B;

    #pragma unroll
    for (int p = 0; p < 3; ++p) {
        const int shift = 24 + p * 8;            // key bits [8,32)

        for (int k = tid; k < 256 * WARPS; k += STHREADS) hist[k] = 0;
        __syncthreads();

        const unsigned long long* sp = src + w * IPW + lane;

        for (int j = 0; j < JITER; ++j) {
            unsigned d = (unsigned)(sp[j * 32] >> shift) & 255u;
            atomicAdd(&hist[d * WARPS + w], 1u);
        }
        __syncthreads();

        unsigned vals[8], sum = 0;
        {
            const int base = tid * 8;
            #pragma unroll
            for (int i = 0; i < 8; ++i) { vals[i] = hist[base + i]; sum += vals[i]; }
        }
        unsigned x = sum;
        #pragma unroll
        for (int d = 1; d < 32; d <<= 1) {
            unsigned y = __shfl_up_sync(FULL, x, d);
            if (lane >= d) x += y;
        }
        if (lane == 31) warpAgg[w] = x;
        __syncthreads();
        if (w == 0) {
            unsigned ww = warpAgg[lane];
            #pragma unroll
            for (int d = 1; d < 32; d <<= 1) {
                unsigned y = __shfl_up_sync(FULL, ww, d);
                if (lane >= d) ww += y;
            }
            warpAgg[lane] = ww;
        }
        __syncthreads();
        {
            unsigned excl = ((w > 0) ? warpAgg[w - 1] : 0u) + (x - sum);
            const int base = tid * 8;
            unsigned run = excl;
            #pragma unroll
            for (int i = 0; i < 8; ++i) { hist[base + i] = run; run += vals[i]; }
        }
        __syncthreads();

        for (int j = 0; j < JITER; ++j) {
            unsigned long long v = sp[j * 32];
            unsigned d = (unsigned)(v >> shift) & 255u;
            unsigned mask = __match_any_sync(FULL, d);
            int leader = __ffs(mask) - 1;
            unsigned prior = __popc(mask & ((1u << lane) - 1u));
            unsigned base = 0;
            if (lane == leader) {
                base = hist[d * WARPS + w];
                hist[d * WARPS + w] = base + __popc(mask);
            }
            base = __shfl_sync(mask, base, leader);
            dst[base + prior] = v;
        }
        __syncthreads();

        unsigned long long* t = src; src = dst; dst = t;
    }
}

// ---------------------------------------------------------------------------
// Kernel 2: hybrid block-find / warp-claim Kruskal
// ---------------------------------------------------------------------------
__global__ __launch_bounds__(KTHREADS, 1)
void malis_kruskal(const void* __restrict__ gt) {
    extern __shared__ unsigned char raw[];
    KSmem* s = reinterpret_cast<KSmem*>(raw);

    const int b    = blockIdx.x;
    const int tid  = threadIdx.x;
    const int lane = tid & 31;
    const int wid  = tid >> 5;

    // groundtruth dtype detection (int64 vs int32); labels in [0,64)
    if (tid == 0) {
        int is64 = 1;
        const long long* g64 = (const long long*)gt;
        for (int i = 0; i < 128; ++i) {
            long long v = g64[i];
            if (v < 0 || v > 63) { is64 = 0; break; }
        }
        s->flag64 = is64;
        s->sDone = 0;
    }
    if (tid < 64) s->hist[tid] = 0;
    __syncthreads();

    const int f64 = s->flag64;
    for (int n = tid; n < NNODE; n += KTHREADS) {
        int lab = f64 ? (int)((const long long*)gt)[(size_t)b * NNODE + n]
                      : ((const int*)gt)[(size_t)b * NNODE + n];
        s->parent[n] = (unsigned short)n;
        s->szn[n]    = 1u | ((lab != 0) ? (1u << 16) : 0u);
        s->claim[n]  = 0u;
        atomicAdd(&s->hist[lab & 63], 1);
    }
    __syncthreads();

    const unsigned long long* P = g_pairB[b];
    unsigned short* parent = s->parent;

    double S = 0.0;                    // warp 0 accumulates
    int mergeCnt = 0;                  // warp 0 only
    const unsigned bit = 1u << lane;
    const unsigned below = bit - 1u;

    unsigned long long cur = P[tid];   // prefetch super-batch 0

    for (int c0 = 0; c0 < NEDGE; c0 += KTHREADS) {
        // ---------------- front-end: all 256 threads --------------------------
        const int nc = (c0 + KTHREADS < NEDGE) ? c0 + KTHREADS : c0;
        const unsigned long long nxt = P[nc + tid];

        {
            const int idx = (int)(cur & 0xFFFFu);
            const unsigned key = (unsigned)(cur >> 16);

            int u, v;
            if (idx < NNODE) {                         // channel 0: (i,j)-(i+1,j)
                u = idx; v = idx + WW;
                if (idx >= NNODE - WW) { u = 0; v = 0; }
            } else {                                   // channel 1: (i,j)-(i,j+1)
                const int t2 = idx - NNODE;
                u = t2; v = t2 + 1;
                if ((t2 & (WW - 1)) == (WW - 1)) { u = 0; v = 0; }
            }

            const unsigned okey = ~key;
            const float a = (okey & 0x80000000u) ? __uint_as_float(okey & 0x7FFFFFFFu)
                                                 : __uint_as_float(~okey);

            // parallel speculative finds (exact at this instant: no merges in flight)
            s->sU[tid]  = u;
            s->sV[tid]  = v;
            s->sRu[tid] = uf_find_halve(parent, u);
            s->sRv[tid] = uf_find_halve(parent, v);
            s->sAf[tid] = a;
        }
        __syncthreads();

        // ---------------- back-end: warp 0, 8 sub-batches of 32 ---------------
        if (wid == 0) {
            for (int sub = 0; sub < 8; ++sub) {
                const int sl = sub * 32 + lane;
                const int u = s->sU[sl];
                const int v = s->sV[sl];
                const float a = s->sAf[sl];

                // touch-up finds from staged spec roots (stale by few merges)
                int ru = uf_find_halve(parent, s->sRu[sl]);
                int rv = uf_find_halve(parent, s->sRv[sl]);

                bool active = (ru != rv);
                unsigned actmask = __ballot_sync(FULL, active);

                while (actmask) {
                    // ---- claim phase: bitmask OR into both roots ----
                    if (active) {
                        atomicOr(&s->claim[ru], bit);
                        atomicOr(&s->claim[rv], bit);
                    }
                    __syncwarp();

                    unsigned mu = 0, mv = 0;
                    if (active) { mu = s->claim[ru]; mv = s->claim[rv]; }
                    const bool headU = active && ((mu & (0u - mu)) == bit);
                    const bool headV = active && ((mv & (0u - mv)) == bit);
                    const bool winB  = headU && headV;
                    const bool wonOne = active && (headU != headV);

                    const int gR = headU ? rv : ru;     // lost root
                    const int oR = headU ? ru : rv;     // won root
                    const unsigned mg = headU ? mv : mu;

                    unsigned zo = 0;
                    if (wonOne) zo = s->szn[oR];
                    s->stage[lane] = zo;

                    const int matchval = wonOne ? gR : (0x20000 + lane);
                    const unsigned grp = __match_any_sync(FULL, matchval);

                    const int h = wonOne ? (__ffs(mg) - 1) : 0;
                    const unsigned wbM = __ballot_sync(FULL, winB);
                    const bool headOK = wonOne && ((wbM >> h) & 1u);

                    unsigned z1 = 0, z2 = 0;
                    if (winB) { z1 = s->szn[ru]; z2 = s->szn[rv]; }
                    int Rw = 0, smallw = 0; unsigned zsumw = 0, zsw = 0;
                    if (winB) {
                        if ((z1 & 0xFFFFu) >= (z2 & 0xFFFFu)) { Rw = ru; smallw = rv; zsw = z2; }
                        else                                   { Rw = rv; smallw = ru; zsw = z1; }
                        zsumw = z1 + z2;    // packed; sz<=16384, nz<=sz: no carry
                    }

                    const int hsrc = headOK ? h : 0;
                    const int hru  = __shfl_sync(FULL, ru, hsrc);
                    const int hrv  = __shfl_sync(FULL, rv, hsrc);
                    const int Rh   = __shfl_sync(FULL, Rw, hsrc);
                    const unsigned hzsum = __shfl_sync(FULL, zsumw, hsrc);

                    const int oh = (gR == hru) ? hrv : hru;
                    unsigned moh = 0;
                    if (headOK) moh = s->claim[oh];

                    const bool rawOK = headOK
                        && ((mg  & below & ~grp & ~(1u << h)) == 0u)
                        && ((moh & below & ~(1u << h)) == 0u);

                    const unsigned blockedM = __ballot_sync(FULL, wonOne && !rawOK);
                    const bool qual = rawOK && ((blockedM & grp & below) == 0u);
                    const unsigned qM = __ballot_sync(FULL, qual);

                    unsigned prefZ = 0;
                    if (qual) {
                        unsigned pm = qM & grp & below;
                        while (pm) {
                            int j = __ffs(pm) - 1; pm &= pm - 1;
                            prefZ += s->stage[j];
                        }
                    }

                    // ---- merge phase (roots pairwise disjoint across winners;
                    //      sizes read pre-merge; size updates atomic) ----
                    if (winB) {
                        parent[smallw] = (unsigned short)Rw;
                        atomicAdd(&s->szn[Rw], zsw);
                        S += (double)((z1 >> 16) * (z2 >> 16)) * (double)a;
                        parent[u] = (unsigned short)Rw;
                        parent[v] = (unsigned short)Rw;
                    }
                    if (qual) {
                        parent[oR] = (unsigned short)Rh;
                        atomicAdd(&s->szn[Rh], zo);
                        const unsigned basenz = (hzsum >> 16) + (prefZ >> 16);
                        S += (double)((zo >> 16) * basenz) * (double)a;
                        parent[u] = (unsigned short)Rh;
                        parent[v] = (unsigned short)Rh;
                    }
                    __syncwarp();

                    if (active) { s->claim[ru] = 0u; s->claim[rv] = 0u; }

                    mergeCnt += __popc(wbM) + __popc(qM);
                    if (winB || qual) active = false;
                    __syncwarp();

                    if (active) {
                        ru = uf_find_halve(parent, ru);
                        rv = uf_find_halve(parent, rv);
                        if (ru == rv) active = false;
                    }
                    actmask = __ballot_sync(FULL, active);
                }

                if (mergeCnt == NNODE - 1) {
                    if (lane == 0) s->sDone = 1;
                    break;
                }
            }
        }
        __syncthreads();
        if (s->sDone) break;   // uniform: all threads observe post-barrier
        cur = nxt;
    }

    // warp 0 reduces and writes the result
    if (wid == 0) {
        #pragma unroll
        for (int d = 16; d > 0; d >>= 1)
            S += __shfl_xor_sync(FULL, S, d);

        if (lane == 0) {
            double Ploc = 0.0;
            for (int l = 1; l < 64; ++l) {
                double c = (double)s->hist[l];
                Ploc += 0.5 * c * (c - 1.0);
            }
            g_res[b] = S - Ploc;
        }
    }
}

__global__ void malis_finalize(float* __restrict__ out) {
    out[0] = (float)(-0.5 * (g_res[0] + g_res[1]));
}

extern "C" void kernel_launch(void* const* d_in, const int* in_sizes, int n_in,
                              void* d_out, int out_size) {
    const float* aff = (const float*)d_in[0];
    const void*  gt  = d_in[1];
    (void)in_sizes; (void)n_in; (void)out_size;

    const int ksmem = (int)sizeof(KSmem);
    cudaFuncSetAttribute(malis_kruskal, cudaFuncAttributeMaxDynamicSharedMemorySize, ksmem);

    malis_sort<<<NB, STHREADS>>>(aff);
    malis_kruskal<<<NB, KTHREADS, ksmem>>>(gt);
    malis_finalize<<<1, 1>>>((float*)d_out);
}